// round 16
// baseline (speedup 1.0000x reference)
#include <cuda_runtime.h>
#include <cuda_bf16.h>
#include <cstdint>
#include <math.h>

#define BB 48
#define SS 512
#define HH 768
#define EE 128
#define LL 16
#define PP 256
#define NERC 11
#define NER_TOTAL (BB*SS*NERC)   // 270336

// ---------------- scratch (device globals; no allocation allowed) -------------
__device__ __align__(16) float g_x  [BB*EE*HH];
__device__ __align__(16) float g_xn [BB*EE*HH];
__device__ __align__(16) float g_sim[BB*EE*EE];
__device__ unsigned char g_Adj[BB*EE*EE];
__device__ __align__(16) float g_h1 [BB*EE*512];
__device__ float g_s1 [BB*EE*4];
__device__ float g_d1 [BB*EE*4];
__device__ __align__(16) float g_h2 [BB*EE*64];
__device__ float g_s2 [BB*EE];
__device__ float g_d2 [BB*EE];
__device__ __align__(16) float g_ent[BB*EE*64];
__device__ __align__(16) float g_clsp[BB*256];
__device__ __align__(16) float g_hid[BB*SS*256];
__device__ __align__(16) float g_He [BB*EE*256];
__device__ __align__(16) float g_Te [BB*EE*256];
__device__ __align__(16) float g_Rp [9*256];
// packed mma fragments: uint4 per (tile16, kchunk, lane)
__device__ uint4 g_pSh[1536*48*32];
__device__ uint4 g_pSl[1536*48*32];
__device__ uint4 g_pXh[384*48*32];
__device__ uint4 g_pXl[384*48*32];
__device__ uint4 g_pW1h[16*48*32];
__device__ uint4 g_pW1l[16*48*32];
__device__ uint4 g_pG1h[32*48*32];
__device__ uint4 g_pG1l[32*48*32];

// ---------------- helpers ----------------
__device__ __forceinline__ unsigned long long ffma2(unsigned long long a,
                                                    unsigned long long b,
                                                    unsigned long long c){
    unsigned long long d;
    asm("fma.rn.f32x2 %0, %1, %2, %3;" : "=l"(d) : "l"(a), "l"(b), "l"(c));
    return d;
}
union F2U { unsigned long long u; float2 f; };
__device__ __forceinline__ void cpa16(void* s, const void* g){
    unsigned sa = (unsigned)__cvta_generic_to_shared(s);
    asm volatile("cp.async.ca.shared.global [%0], [%1], 16;" :: "r"(sa), "l"(g));
}
__device__ __forceinline__ void mma16816(float* c, const unsigned* a, const unsigned* b){
    asm volatile("mma.sync.aligned.m16n8k16.row.col.f32.bf16.bf16.f32 "
        "{%0,%1,%2,%3}, {%4,%5,%6,%7}, {%8,%9}, {%0,%1,%2,%3};"
        : "+f"(c[0]), "+f"(c[1]), "+f"(c[2]), "+f"(c[3])
        : "r"(a[0]), "r"(a[1]), "r"(a[2]), "r"(a[3]), "r"(b[0]), "r"(b[1]));
}
__device__ __forceinline__ void bsplit2(float x, float y, unsigned& h, unsigned& l){
    __nv_bfloat16 hx = __float2bfloat16(x);
    __nv_bfloat16 hy = __float2bfloat16(y);
    __nv_bfloat16 lx = __float2bfloat16(x - __bfloat162float(hx));
    __nv_bfloat16 ly = __float2bfloat16(y - __bfloat162float(hy));
    unsigned short ux = *(unsigned short*)&hx, uy = *(unsigned short*)&hy;
    unsigned short vx = *(unsigned short*)&lx, vy = *(unsigned short*)&ly;
    h = (unsigned)ux | ((unsigned)uy << 16);
    l = (unsigned)vx | ((unsigned)vy << 16);
}

// ============================================================================
// pack_a: fp32 A[M,768] -> packed fragment uint4 arrays (hi, lo).
// ============================================================================
__global__ __launch_bounds__(256) void pack_a(const float* __restrict__ A,
                                              uint4* __restrict__ oh,
                                              uint4* __restrict__ ol)
{
    int unit = blockIdx.x*8 + (threadIdx.x >> 5);
    int lane = threadIdx.x & 31;
    int tile = unit / 48, c = unit % 48;
    int g = lane >> 2, tg = lane & 3;
    const float* base = A + (size_t)tile*16*HH + c*16;
    float2 r0 = *(const float2*)(base + (size_t)g*HH + tg*2);
    float2 r1 = *(const float2*)(base + (size_t)(g+8)*HH + tg*2);
    float2 r2 = *(const float2*)(base + (size_t)g*HH + 8 + tg*2);
    float2 r3 = *(const float2*)(base + (size_t)(g+8)*HH + 8 + tg*2);
    uint4 H, L;
    bsplit2(r0.x, r0.y, H.x, L.x);
    bsplit2(r1.x, r1.y, H.y, L.y);
    bsplit2(r2.x, r2.y, H.z, L.z);
    bsplit2(r3.x, r3.y, H.w, L.w);
    size_t o = (size_t)unit*32 + lane;
    oh[o] = H; ol[o] = L;
}

// ============================================================================
// pack_b: fp32 W[768,N] (k-major) -> transposed packed B fragments.
// ============================================================================
__global__ __launch_bounds__(256) void pack_b(const float* __restrict__ W, int N,
                                              uint4* __restrict__ oh,
                                              uint4* __restrict__ ol)
{
    int unit = blockIdx.x*8 + (threadIdx.x >> 5);
    int lane = threadIdx.x & 31;
    int nt = unit / 48, c = unit % 48;
    int g = lane >> 2, tg = lane & 3;
    const float* p = W + (size_t)(c*16)*N + nt*16;
    float x0 = p[(tg*2)*N + g],       x1 = p[(tg*2+1)*N + g];
    float x2 = p[(8+tg*2)*N + g],     x3 = p[(8+tg*2+1)*N + g];
    float x4 = p[(tg*2)*N + g+8],     x5 = p[(tg*2+1)*N + g+8];
    float x6 = p[(8+tg*2)*N + g+8],   x7 = p[(8+tg*2+1)*N + g+8];
    uint4 H, L;
    bsplit2(x0, x1, H.x, L.x);
    bsplit2(x2, x3, H.y, L.y);
    bsplit2(x4, x5, H.z, L.z);
    bsplit2(x6, x7, H.w, L.w);
    size_t o = (size_t)unit*32 + lane;
    oh[o] = H; ol[o] = L;
}

// ============================================================================
// mma_merged: both big GEMMs in one launch (576 tiles of 128x128x768).
// ============================================================================
__global__ __launch_bounds__(256, 2) void mma_merged(
    const uint4* __restrict__ Sh, const uint4* __restrict__ Sl,
    const uint4* __restrict__ W1h, const uint4* __restrict__ W1l,
    const uint4* __restrict__ Xh, const uint4* __restrict__ Xl,
    const uint4* __restrict__ G1h, const uint4* __restrict__ G1l,
    const float* __restrict__ b_ner1)
{
    extern __shared__ __align__(16) uint4 sm4[];   // 4 slots x 1024 uint4 = 64KB
    int bid = blockIdx.x;
    int tid = threadIdx.x, lane = tid & 31, wid = tid >> 5;
    int wm = wid & 3, wn = wid >> 2;
    int g = lane >> 2, tg = lane & 3;

    const uint4 *Ah, *Al, *Bh, *Bl;
    float* C; const float* bias;
    int N, m0, n0, dorelu;
    if (bid < 384){
        m0 = (bid >> 1)*128; n0 = (bid & 1)*128;
        Ah = Sh; Al = Sl; Bh = W1h; Bl = W1l;
        C = g_hid; N = 256; bias = b_ner1; dorelu = 1;
    } else {
        int b2 = bid - 384;
        m0 = (b2 >> 2)*128; n0 = (b2 & 3)*128;
        Ah = Xh; Al = Xl; Bh = G1h; Bl = G1l;
        C = g_h1; N = 512; bias = nullptr; dorelu = 0;
    }

    float acc[2][8][4];
    #pragma unroll
    for (int mt=0;mt<2;mt++)
        #pragma unroll
        for (int nt=0;nt<8;nt++)
            #pragma unroll
            for (int q=0;q<4;q++) acc[mt][nt][q] = 0.f;

    const uint4* srcs[4];
    int dsti[4];
    #pragma unroll
    for (int q=0;q<4;q++){
        int idx = tid + 256*q;
        int seg = idx >> 5, l2 = idx & 31;
        int t = seg & 7;
        const uint4* base;
        size_t ub;
        if (seg < 8)       { base = Ah; ub = (size_t)((m0>>4)+t)*48*32; }
        else if (seg < 16) { base = Al; ub = (size_t)((m0>>4)+t)*48*32; }
        else if (seg < 24) { base = Bh; ub = (size_t)((n0>>4)+t)*48*32; }
        else               { base = Bl; ub = (size_t)((n0>>4)+t)*48*32; }
        srcs[q] = base + ub + l2;
        dsti[q] = idx;
    }

    #pragma unroll
    for (int s=0; s<3; s++){
        #pragma unroll
        for (int q=0;q<4;q++)
            cpa16(&sm4[s*1024 + dsti[q]], srcs[q] + s*32);
        asm volatile("cp.async.commit_group;");
    }

    for (int c = 0; c < 48; c++){
        asm volatile("cp.async.wait_group 2;");
        __syncthreads();
        if (c + 3 < 48){
            #pragma unroll
            for (int q=0;q<4;q++)
                cpa16(&sm4[((c+3)&3)*1024 + dsti[q]], srcs[q] + (c+3)*32);
        }
        asm volatile("cp.async.commit_group;");

        const uint4* slot = &sm4[(c & 3)*1024];
        uint4 b4H[4], b4L[4];
        #pragma unroll
        for (int j=0;j<4;j++){
            b4H[j] = slot[(16 + wn*4 + j)*32 + lane];
            b4L[j] = slot[(24 + wn*4 + j)*32 + lane];
        }
        #pragma unroll
        for (int mt=0; mt<2; mt++){
            uint4 a4H = slot[(wm*2 + mt)*32 + lane];
            uint4 a4L = slot[(8 + wm*2 + mt)*32 + lane];
            unsigned aH[4] = {a4H.x, a4H.y, a4H.z, a4H.w};
            unsigned aL[4] = {a4L.x, a4L.y, a4L.z, a4L.w};
            #pragma unroll
            for (int j=0; j<4; j++){
                unsigned bHe[2] = {b4H[j].x, b4H[j].y};
                unsigned bHo[2] = {b4H[j].z, b4H[j].w};
                unsigned bLe[2] = {b4L[j].x, b4L[j].y};
                unsigned bLo[2] = {b4L[j].z, b4L[j].w};
                mma16816(acc[mt][2*j],   aH, bHe);
                mma16816(acc[mt][2*j],   aH, bLe);
                mma16816(acc[mt][2*j],   aL, bHe);
                mma16816(acc[mt][2*j+1], aH, bHo);
                mma16816(acc[mt][2*j+1], aH, bLo);
                mma16816(acc[mt][2*j+1], aL, bHo);
            }
        }
    }

    #pragma unroll
    for (int mt=0; mt<2; mt++){
        int rbase = m0 + wm*32 + mt*16 + g;
        #pragma unroll
        for (int nt=0; nt<8; nt++){
            int col = n0 + wn*64 + nt*8 + tg*2;
            float b0 = 0.f, b1 = 0.f;
            if (bias){ b0 = bias[col]; b1 = bias[col+1]; }
            float v0 = acc[mt][nt][0] + b0, v1 = acc[mt][nt][1] + b1;
            float v2 = acc[mt][nt][2] + b0, v3 = acc[mt][nt][3] + b1;
            if (dorelu){
                v0 = fmaxf(v0,0.f); v1 = fmaxf(v1,0.f);
                v2 = fmaxf(v2,0.f); v3 = fmaxf(v3,0.f);
            }
            *(float2*)&C[(size_t)rbase*N + col]     = make_float2(v0, v1);
            *(float2*)&C[(size_t)(rbase+8)*N + col] = make_float2(v2, v3);
        }
    }
}

// ============================================================================
// Small-GEMM (He/Te merged): FFMA2, 64x128 tile; blockIdx.z picks He vs Te.
// ============================================================================
__global__ __launch_bounds__(128, 3) void gemm_kernel(
    const float* __restrict__ Bbase, int ldb, int K)
{
    __shared__ __align__(16) float2 As2[2][16][64];
    __shared__ __align__(16) float  Bs [2][16][128];

    const float* A = g_ent;
    const float* B = Bbase + (size_t)blockIdx.z * 64 * 256;
    float* C = blockIdx.z ? g_Te : g_He;

    int tid = threadIdx.x;
    int tm = tid >> 4, tn = tid & 15;
    int m0 = blockIdx.x * 64, n0 = blockIdx.y * 128;
    int nch = K >> 4;

    unsigned long long acc[8][4];
    #pragma unroll
    for (int i=0;i<8;i++)
        #pragma unroll
        for (int p=0;p<4;p++) acc[i][p] = 0ull;

    int lr = tid >> 1, lc8 = (tid & 1) * 8;
    const float* aP = A + (size_t)(m0 + lr) * K + lc8;
    int bkk[4], bc4[4];
    #pragma unroll
    for (int i=0;i<4;i++){ int q = i*128 + tid; bkk[i] = q >> 5; bc4[i] = (q & 31) * 4; }

    float4 pa0, pa1;
    pa0 = *(const float4*)(aP);
    pa1 = *(const float4*)(aP + 4);
    #pragma unroll
    for (int i=0;i<4;i++)
        cpa16(&Bs[0][bkk[i]][bc4[i]], B + (size_t)bkk[i]*ldb + n0 + bc4[i]);
    asm volatile("cp.async.commit_group;");
    {
        float v[8] = {pa0.x,pa0.y,pa0.z,pa0.w,pa1.x,pa1.y,pa1.z,pa1.w};
        #pragma unroll
        for (int j=0;j<8;j++) As2[0][lc8+j][lr] = make_float2(v[j],v[j]);
    }

    for (int c = 0; c < nch; c++){
        int cb = c & 1, nb = cb ^ 1;
        if (c + 1 < nch){
            int k0n = (c+1)*16;
            pa0 = *(const float4*)(aP + k0n);
            pa1 = *(const float4*)(aP + k0n + 4);
            #pragma unroll
            for (int i=0;i<4;i++)
                cpa16(&Bs[nb][bkk[i]][bc4[i]],
                      B + (size_t)(k0n + bkk[i])*ldb + n0 + bc4[i]);
            asm volatile("cp.async.commit_group;");
            asm volatile("cp.async.wait_group 1;");
        } else {
            asm volatile("cp.async.wait_group 0;");
        }
        __syncthreads();
        #pragma unroll
        for (int kk=0;kk<16;kk++){
            unsigned long long b2[4];
            #pragma unroll
            for (int p=0;p<4;p++)
                b2[p] = *(const unsigned long long*)&Bs[cb][kk][2*(tn + 16*p)];
            #pragma unroll
            for (int i=0;i<8;i++){
                unsigned long long a2 =
                    *(const unsigned long long*)&As2[cb][kk][tm*8+i];
                acc[i][0] = ffma2(a2, b2[0], acc[i][0]);
                acc[i][1] = ffma2(a2, b2[1], acc[i][1]);
                acc[i][2] = ffma2(a2, b2[2], acc[i][2]);
                acc[i][3] = ffma2(a2, b2[3], acc[i][3]);
            }
        }
        __syncthreads();
        if (c + 1 < nch){
            float v[8] = {pa0.x,pa0.y,pa0.z,pa0.w,pa1.x,pa1.y,pa1.z,pa1.w};
            #pragma unroll
            for (int j=0;j<8;j++) As2[nb][lc8+j][lr] = make_float2(v[j],v[j]);
        }
    }

    #pragma unroll
    for (int i=0;i<8;i++){
        size_t row = m0 + tm*8 + i;
        #pragma unroll
        for (int p=0;p<4;p++){
            F2U u; u.u = acc[i][p];
            *(float2*)&C[row*ldb + n0 + 32*p + 2*tn] = u.f;
        }
    }
}

// ============================================================================
// ner_head: out = g_hid @ W2 + b2.
// ============================================================================
__global__ __launch_bounds__(256) void ner_head(
    const float* __restrict__ W2, const float* __restrict__ b2,
    float* __restrict__ out)
{
    __shared__ float W2t[NERC][256];
    __shared__ float b2s[NERC];
    int tid = threadIdx.x;
    for (int i = tid; i < 256*NERC; i += 256){
        int c = i / NERC, jo = i % NERC;
        W2t[jo][c] = W2[i];
    }
    if (tid < NERC) b2s[tid] = b2[tid];
    __syncthreads();
    int w = tid >> 5, lane = tid & 31;
    int row = blockIdx.x*8 + w;
    const float* hr = &g_hid[(size_t)row*256 + lane*8];
    float4 v0 = *(const float4*)hr;
    float4 v1 = *(const float4*)(hr + 4);
    #pragma unroll
    for (int jo = 0; jo < NERC; jo++){
        const float* wr = &W2t[jo][lane*8];
        float4 w0 = *(const float4*)wr;
        float4 w1 = *(const float4*)(wr + 4);
        float p = 0.f;
        p = fmaf(v0.x, w0.x, p); p = fmaf(v0.y, w0.y, p);
        p = fmaf(v0.z, w0.z, p); p = fmaf(v0.w, w0.w, p);
        p = fmaf(v1.x, w1.x, p); p = fmaf(v1.y, w1.y, p);
        p = fmaf(v1.z, w1.z, p); p = fmaf(v1.w, w1.w, p);
        #pragma unroll
        for (int off=16;off>0;off>>=1) p += __shfl_xor_sync(0xffffffffu,p,off);
        if (lane == 0) out[row*NERC + jo] = p + b2s[jo];
    }
}

// ============================================================================
// pool_kernel: loads only len+1 token rows.
// ============================================================================
__global__ __launch_bounds__(256) void pool_kernel(
    const float* __restrict__ seq, const int* __restrict__ span_start,
    const int* __restrict__ span_len, const int* __restrict__ ent_type,
    const float* __restrict__ type_emb)
{
    extern __shared__ float tok[];
    __shared__ float meanv[HH];
    __shared__ float sc[LL];
    __shared__ float wv[LL];
    __shared__ float red[8];

    int be = blockIdx.x;
    int b = be / EE;
    int tid = threadIdx.x;
    int start = span_start[be];
    int len = span_len[be];
    float cnt = (float)(len + 1);

    const float4* src = (const float4*)&seq[(size_t)(b*SS + start)*HH];
    float4* dst4 = (float4*)tok;
    int nv4 = (len + 1) * (HH/4);
    for (int q = tid; q < nv4; q += 256) dst4[q] = src[q];
    __syncthreads();

    for (int d = tid; d < HH; d += 256){
        float s = 0.f;
        for (int l = 0; l <= len; l++) s += tok[l*HH + d];
        meanv[d] = s / cnt;
    }
    __syncthreads();

    int w = tid >> 5, lane = tid & 31;
    for (int l = w; l <= len; l += 8){
        float p = 0.f;
        for (int d = lane; d < HH; d += 32) p = fmaf(tok[l*HH+d], meanv[d], p);
        #pragma unroll
        for (int off=16;off>0;off>>=1) p += __shfl_xor_sync(0xffffffffu,p,off);
        if (lane==0) sc[l] = p;
    }
    __syncthreads();

    if (tid == 0){
        float mx = -1e30f;
        for (int l=0;l<=len;l++) mx = fmaxf(mx, sc[l]);
        float s = 0.f;
        for (int l=0;l<=len;l++){ float e = expf(sc[l]-mx); wv[l]=e; s+=e; }
        float inv = 1.f/s;
        for (int l=0;l<=len;l++) wv[l] *= inv;
        for (int l=len+1;l<LL;l++) wv[l] = 0.f;
    }
    __syncthreads();

    const float* te = &type_emb[ent_type[be]*HH];
    float xv[3]; float nsq = 0.f;
    #pragma unroll
    for (int q = 0; q < 3; q++){
        int d = tid + q*256;
        float p = 0.f;
        for (int l = 0; l <= len; l++) p = fmaf(wv[l], tok[l*HH+d], p);
        float v = p + te[d];
        xv[q] = v;
        g_x[(size_t)be*HH + d] = v;
        nsq = fmaf(v, v, nsq);
    }
    #pragma unroll
    for (int off=16;off>0;off>>=1) nsq += __shfl_xor_sync(0xffffffffu,nsq,off);
    if (lane==0) red[w] = nsq;
    __syncthreads();
    float tot = 0.f;
    #pragma unroll
    for (int i=0;i<8;i++) tot += red[i];
    float inv = 1.f / fmaxf(sqrtf(tot), 1e-12f);
    #pragma unroll
    for (int q=0;q<3;q++){
        int d = tid + q*256;
        g_xn[(size_t)be*HH + d] = xv[q]*inv;
    }
}

// ============================================================================
// sim_kernel (FFMA2)
// ============================================================================
__global__ __launch_bounds__(128) void sim_kernel()
{
    __shared__ __align__(16) float2 As2[2][16][64];
    __shared__ float Xt[2][16][132];

    int b = blockIdx.x >> 1;
    int i0 = (blockIdx.x & 1) * 64;
    const float* X = &g_xn[(size_t)b*EE*HH];
    int tid = threadIdx.x;
    int tm = tid >> 4, tn = tid & 15;

    unsigned long long acc[8][4];
    #pragma unroll
    for (int i=0;i<8;i++)
        #pragma unroll
        for (int p=0;p<4;p++) acc[i][p] = 0ull;

    int ar = tid >> 1, akq = (tid & 1) * 8;
    const float* aP = X + (size_t)(i0 + ar)*HH + akq;
    const float* xP = X + (size_t)tid*HH;

    float4 pa0, pa1, px[4];
    pa0 = *(const float4*)(aP);
    pa1 = *(const float4*)(aP + 4);
    #pragma unroll
    for (int q=0;q<4;q++) px[q] = *(const float4*)(xP + 4*q);
    {
        float v[8] = {pa0.x,pa0.y,pa0.z,pa0.w,pa1.x,pa1.y,pa1.z,pa1.w};
        #pragma unroll
        for (int j=0;j<8;j++) As2[0][akq+j][ar] = make_float2(v[j],v[j]);
        #pragma unroll
        for (int q=0;q<4;q++){
            Xt[0][4*q+0][tid] = px[q].x;
            Xt[0][4*q+1][tid] = px[q].y;
            Xt[0][4*q+2][tid] = px[q].z;
            Xt[0][4*q+3][tid] = px[q].w;
        }
    }

    for (int c = 0; c < 48; c++){
        int cb = c & 1, nb = cb ^ 1;
        __syncthreads();
        if (c + 1 < 48){
            int k0n = (c+1)*16;
            pa0 = *(const float4*)(aP + k0n);
            pa1 = *(const float4*)(aP + k0n + 4);
            #pragma unroll
            for (int q=0;q<4;q++) px[q] = *(const float4*)(xP + k0n + 4*q);
        }
        #pragma unroll
        for (int kk=0;kk<16;kk++){
            unsigned long long b2[4];
            #pragma unroll
            for (int p=0;p<4;p++)
                b2[p] = *(const unsigned long long*)&Xt[cb][kk][2*(tn + 16*p)];
            #pragma unroll
            for (int i=0;i<8;i++){
                unsigned long long a2 =
                    *(const unsigned long long*)&As2[cb][kk][tm*8+i];
                acc[i][0] = ffma2(a2, b2[0], acc[i][0]);
                acc[i][1] = ffma2(a2, b2[1], acc[i][1]);
                acc[i][2] = ffma2(a2, b2[2], acc[i][2]);
                acc[i][3] = ffma2(a2, b2[3], acc[i][3]);
            }
        }
        if (c + 1 < 48){
            float v[8] = {pa0.x,pa0.y,pa0.z,pa0.w,pa1.x,pa1.y,pa1.z,pa1.w};
            #pragma unroll
            for (int j=0;j<8;j++) As2[nb][akq+j][ar] = make_float2(v[j],v[j]);
            #pragma unroll
            for (int q=0;q<4;q++){
                Xt[nb][4*q+0][tid] = px[q].x;
                Xt[nb][4*q+1][tid] = px[q].y;
                Xt[nb][4*q+2][tid] = px[q].z;
                Xt[nb][4*q+3][tid] = px[q].w;
            }
        }
    }

    float* simb = &g_sim[(size_t)b*EE*EE];
    #pragma unroll
    for (int i=0;i<8;i++){
        int row = i0 + tm*8 + i;
        #pragma unroll
        for (int p=0;p<4;p++){
            F2U u; u.u = acc[i][p];
            *(float2*)&simb[row*EE + 2*(tn + 16*p)] = u.f;
        }
    }
}

// ============================================================================
// topk_kernel
// ============================================================================
__global__ __launch_bounds__(256) void topk_kernel()
{
    int w = threadIdx.x >> 5, lane = threadIdx.x & 31;
    int row = blockIdx.x*8 + w;
    int i = row & 127;
    const float* r = &g_sim[(size_t)row*EE];
    float v[4];
    #pragma unroll
    for (int q=0;q<4;q++) v[q] = r[lane + q*32];
    unsigned used = 0;
    int pick[6]; float pval[6];
    for (int k=0;k<6;k++){
        float bv = -1e30f; int bj = 128;
        #pragma unroll
        for (int q=0;q<4;q++){
            if (!((used>>q)&1u)){
                int j = lane + q*32;
                if (v[q] > bv){ bv = v[q]; bj = j; }
            }
        }
        #pragma unroll
        for (int off=16; off>0; off>>=1){
            float ov = __shfl_xor_sync(0xffffffffu, bv, off);
            int   oj = __shfl_xor_sync(0xffffffffu, bj, off);
            if (ov > bv || (ov == bv && oj < bj)){ bv = ov; bj = oj; }
        }
        pick[k]=bj; pval[k]=bv;
        if ((bj & 31) == lane) used |= 1u << (bj >> 5);
    }
    int jb = lane*4;
    unsigned char c0=0,c1=0,c2=0,c3=0;
    #pragma unroll
    for (int k=0;k<6;k++){
        if (pval[k] > 0.1f && pick[k] != i){
            int d = pick[k] - jb;
            if (d==0) c0=1; else if (d==1) c1=1; else if (d==2) c2=1; else if (d==3) c3=1;
        }
    }
    int ds = i - jb;
    if (ds>=0 && ds<4){ if(ds==0)c0=1; else if(ds==1)c1=1; else if(ds==2)c2=1; else c3=1; }
    *(uchar4*)&g_Adj[(size_t)row*EE + jb] = make_uchar4(c0,c1,c2,c3);
}

// ============================================================================
// sd1_kernel
// ============================================================================
__global__ __launch_bounds__(128) void sd1_kernel(const float* __restrict__ a_src,
                                                  const float* __restrict__ a_dst)
{
    int row = blockIdx.x;
    int hd = threadIdx.x >> 5, lane = threadIdx.x & 31;
    const float* hrow = &g_h1[(size_t)row*512 + hd*128];
    float ps = 0.f, pd = 0.f;
    #pragma unroll
    for (int q=0;q<4;q++){
        float hv = hrow[lane + 32*q];
        ps = fmaf(hv, a_src[hd*128 + lane + 32*q], ps);
        pd = fmaf(hv, a_dst[hd*128 + lane + 32*q], pd);
    }
    #pragma unroll
    for (int off=16;off>0;off>>=1){
        ps += __shfl_xor_sync(0xffffffffu,ps,off);
        pd += __shfl_xor_sync(0xffffffffu,pd,off);
    }
    if (lane==0){ g_s1[row*4+hd]=ps; g_d1[row*4+hd]=pd; }
}

// ============================================================================
// att1_kernel (FUSED with gat2h): computes g1v row in smem, then
// h2 = g1v @ W_g2 (512->64) + s2/d2 dots, all in one block per (b,t).
// ============================================================================
__global__ __launch_bounds__(128) void att1_kernel(
    const float* __restrict__ b_g1, const float* __restrict__ gamma,
    const float* __restrict__ beta, const float* __restrict__ Wg2,
    const float* __restrict__ a_src2, const float* __restrict__ a_dst2)
{
    __shared__ int act[EE];
    __shared__ int wcnt[4], woff[4];
    __shared__ int nact_s;
    __shared__ float wts[4][EE];
    __shared__ float red[4], red2[4];
    __shared__ float ysm[512];
    __shared__ float part2[2][64];
    __shared__ float rs[2], rd[2];

    int be = blockIdx.x;
    int b = be / EE, t = be % EE;
    int tid = threadIdx.x, w = tid>>5, lane = tid&31;

    bool flag = g_Adj[(size_t)(b*EE + tid)*EE + t] != 0;
    unsigned mball = __ballot_sync(0xffffffffu, flag);
    if (lane==0) wcnt[w] = __popc(mball);
    __syncthreads();
    if (tid==0){ int o=0; for (int i2=0;i2<4;i2++){ woff[i2]=o; o+=wcnt[i2]; } nact_s=o; }
    __syncthreads();
    if (flag) act[woff[w] + __popc(mball & ((1u<<lane)-1u))] = tid;
    __syncthreads();
    int nact = nact_s;

    {
        int hd = w;
        float dv = g_d1[be*4 + hd];
        float mx = -1e30f;
        for (int k=lane;k<nact;k+=32){
            float e = g_s1[(b*EE+act[k])*4 + hd] + dv;
            e = e > 0.f ? e : 0.2f*e;
            wts[hd][k] = e;
            mx = fmaxf(mx, e);
        }
        #pragma unroll
        for (int off=16;off>0;off>>=1) mx = fmaxf(mx, __shfl_xor_sync(0xffffffffu,mx,off));
        float sum = 0.f;
        for (int k=lane;k<nact;k+=32){
            float e = expf(wts[hd][k]-mx);
            wts[hd][k] = e; sum += e;
        }
        #pragma unroll
        for (int off=16;off>0;off>>=1) sum += __shfl_xor_sync(0xffffffffu,sum,off);
        float inv = 1.f/sum;
        for (int k=lane;k<nact;k+=32) wts[hd][k] *= inv;
    }
    __syncthreads();

    float ov[4];
    #pragma unroll
    for (int q=0;q<4;q++){
        int f = tid + q*128;
        float o = 0.f;
        for (int k=0;k<nact;k++)
            o = fmaf(wts[q][k], g_h1[(size_t)(b*EE+act[k])*512 + f], o);
        ov[q] = o + b_g1[f];
    }
    float ls = ov[0]+ov[1]+ov[2]+ov[3];
    #pragma unroll
    for (int off=16;off>0;off>>=1) ls += __shfl_xor_sync(0xffffffffu,ls,off);
    if (lane==0) red[w] = ls;
    __syncthreads();
    float mean = (red[0]+red[1]+red[2]+red[3]) * (1.f/512.f);
    float lv = 0.f;
    #pragma unroll
    for (int q=0;q<4;q++){ float d = ov[q]-mean; lv = fmaf(d,d,lv); }
    #pragma unroll
    for (int off=16;off>0;off>>=1) lv += __shfl_xor_sync(0xffffffffu,lv,off);
    if (lane==0) red2[w] = lv;
    __syncthreads();
    float var = (red2[0]+red2[1]+red2[2]+red2[3]) * (1.f/512.f);
    float rstd = rsqrtf(var + 1e-5f);
    #pragma unroll
    for (int q=0;q<4;q++){
        int f = tid + q*128;
        float y = (ov[q]-mean)*rstd*gamma[f] + beta[f];
        y = y > 0.f ? y : expm1f(y);
        ysm[f] = y;
    }
    __syncthreads();

    {
        int col = tid & 63, half = tid >> 6;
        const float* wp = &Wg2[(size_t)(half*256)*64 + col];
        const float* yp = &ysm[half*256];
        float a0=0.f, a1=0.f, a2=0.f, a3=0.f;
        #pragma unroll 4
        for (int k = 0; k < 256; k += 4){
            a0 = fmaf(yp[k],   wp[(size_t)k*64],     a0);
            a1 = fmaf(yp[k+1], wp[(size_t)(k+1)*64], a1);
            a2 = fmaf(yp[k+2], wp[(size_t)(k+2)*64], a2);
            a3 = fmaf(yp[k+3], wp[(size_t)(k+3)*64], a3);
        }
        part2[half][col] = (a0+a1)+(a2+a3);
    }
    __syncthreads();
    if (tid < 64){
        float a = part2[0][tid] + part2[1][tid];
        g_h2[(size_t)be*64 + tid] = a;
        float ps = a * a_src2[tid];
        float pd = a * a_dst2[tid];
        #pragma unroll
        for (int off=16;off>0;off>>=1){
            ps += __shfl_xor_sync(0xffffffffu,ps,off);
            pd += __shfl_xor_sync(0xffffffffu,pd,off);
        }
        if ((tid & 31) == 0){ rs[tid>>5] = ps; rd[tid>>5] = pd; }
    }
    __syncthreads();
    if (tid == 0){ g_s2[be] = rs[0]+rs[1]; g_d2[be] = rd[0]+rd[1]; }
}

// ============================================================================
// att2_kernel
// ============================================================================
__global__ __launch_bounds__(128) void att2_kernel(
    const float* __restrict__ b_g2, const float* __restrict__ gamma,
    const float* __restrict__ beta)
{
    __shared__ int act[EE];
    __shared__ int wcnt[4], woff[4];
    __shared__ int nact_s;
    __shared__ float wts[EE];
    __shared__ float red[2], red2[2];

    int be = blockIdx.x;
    int b = be / EE, t = be % EE;
    int tid = threadIdx.x, w = tid>>5, lane = tid&31;

    bool flag = g_Adj[(size_t)(b*EE + tid)*EE + t] != 0;
    unsigned mball = __ballot_sync(0xffffffffu, flag);
    if (lane==0) wcnt[w] = __popc(mball);
    __syncthreads();
    if (tid==0){ int o=0; for (int i2=0;i2<4;i2++){ woff[i2]=o; o+=wcnt[i2]; } nact_s=o; }
    __syncthreads();
    if (flag) act[woff[w] + __popc(mball & ((1u<<lane)-1u))] = tid;
    __syncthreads();
    int nact = nact_s;

    if (w == 0){
        float dv = g_d2[be];
        float mx = -1e30f;
        for (int k=lane;k<nact;k+=32){
            float e = g_s2[b*EE + act[k]] + dv;
            e = e > 0.f ? e : 0.2f*e;
            wts[k] = e;
            mx = fmaxf(mx, e);
        }
        #pragma unroll
        for (int off=16;off>0;off>>=1) mx = fmaxf(mx, __shfl_xor_sync(0xffffffffu,mx,off));
        float sum = 0.f;
        for (int k=lane;k<nact;k+=32){
            float e = expf(wts[k]-mx);
            wts[k] = e; sum += e;
        }
        #pragma unroll
        for (int off=16;off>0;off>>=1) sum += __shfl_xor_sync(0xffffffffu,sum,off);
        float inv = 1.f/sum;
        for (int k=lane;k<nact;k+=32) wts[k] *= inv;
    }
    __syncthreads();

    float o = 0.f;
    if (tid < 64){
        for (int k=0;k<nact;k++)
            o = fmaf(wts[k], g_h2[(size_t)(b*EE+act[k])*64 + tid], o);
        o += b_g2[tid];
    }
    float ls = (tid<64) ? o : 0.f;
    #pragma unroll
    for (int off=16;off>0;off>>=1) ls += __shfl_xor_sync(0xffffffffu,ls,off);
    if (w < 2 && lane==0) red[w] = ls;
    __syncthreads();
    float mean = (red[0]+red[1]) * (1.f/64.f);
    float dv2 = (tid<64) ? (o-mean) : 0.f;
    float lv = dv2*dv2;
    #pragma unroll
    for (int off=16;off>0;off>>=1) lv += __shfl_xor_sync(0xffffffffu,lv,off);
    if (w < 2 && lane==0) red2[w] = lv;
    __syncthreads();
    float var = (red2[0]+red2[1]) * (1.f/64.f);
    if (tid < 64){
        float y = (o-mean)*rsqrtf(var+1e-5f)*gamma[tid] + beta[tid];
        y = y > 0.f ? y : expm1f(y);
        g_ent[(size_t)be*64 + tid] = y;
    }
}

// ============================================================================
// cls_kernel v2: grid (48, 4); 256 thr = 64 cols x 4 kgroups; smem reduce.
// ============================================================================
__global__ __launch_bounds__(256) void cls_kernel(const float* __restrict__ seq,
                                                  const float* __restrict__ W_r1,
                                                  const float* __restrict__ b_r1)
{
    __shared__ float c[HH];
    __shared__ float part[4][64];
    int b = blockIdx.x, cq = blockIdx.y;
    int tid = threadIdx.x;
    int col = cq*64 + (tid & 63);
    int kg = tid >> 6;
    for (int d = tid; d < HH; d += 256) c[d] = seq[(size_t)b*SS*HH + d];
    __syncthreads();
    float acc = 0.f;
    const float* wp = &W_r1[(size_t)(160 + kg*192)*256 + col];
    #pragma unroll 4
    for (int d = 0; d < 192; d++)
        acc = fmaf(c[kg*192 + d], wp[(size_t)d*256], acc);
    part[kg][tid & 63] = acc;
    __syncthreads();
    if (tid < 64){
        float s = part[0][tid] + part[1][tid] + part[2][tid] + part[3][tid];
        g_clsp[b*256 + col] = s + b_r1[col];
    }
}

__global__ __launch_bounds__(256) void rp_kernel(const float* __restrict__ rel_emb,
                                                 const float* __restrict__ W_r1)
{
    __shared__ float re[32];
    int r = blockIdx.x, tid = threadIdx.x;
    if (tid < 32) re[tid] = rel_emb[r*32 + tid];
    __syncthreads();
    float s = 0.f;
    #pragma unroll 8
    for (int k=0;k<32;k++) s = fmaf(re[k], W_r1[(128+k)*256 + tid], s);
    g_Rp[r*256 + tid] = s;
}

__global__ __launch_bounds__(256) void pair_kernel(
    const int* __restrict__ pair_head, const int* __restrict__ pair_tail,
    const int* __restrict__ pair_rel,  const float* __restrict__ W_r2,
    const float* __restrict__ b_r2,    float* __restrict__ out)
{
    int w = threadIdx.x >> 5, lane = threadIdx.x & 31;
    int bp = blockIdx.x*8 + w;
    int b = bp >> 8;
    int h = pair_head[bp], t = pair_tail[bp], r = pair_rel[bp];
    const float* He = &g_He[(size_t)(b*EE+h)*256 + lane*8];
    const float* Te = &g_Te[(size_t)(b*EE+t)*256 + lane*8];
    const float* Rp = &g_Rp[r*256 + lane*8];
    const float* Cp = &g_clsp[b*256 + lane*8];
    float s = 0.f;
    #pragma unroll
    for (int q=0;q<2;q++){
        float4 a  = *(const float4*)(He + 4*q);
        float4 bb = *(const float4*)(Te + 4*q);
        float4 c  = *(const float4*)(Rp + 4*q);
        float4 d  = *(const float4*)(Cp + 4*q);
        float4 w4 = *(const float4*)&W_r2[lane*8 + 4*q];
        float h0 = fmaxf(a.x+bb.x+c.x+d.x, 0.f); s = fmaf(h0, w4.x, s);
        float h1 = fmaxf(a.y+bb.y+c.y+d.y, 0.f); s = fmaf(h1, w4.y, s);
        float h2 = fmaxf(a.z+bb.z+c.z+d.z, 0.f); s = fmaf(h2, w4.z, s);
        float h3 = fmaxf(a.w+bb.w+c.w+d.w, 0.f); s = fmaf(h3, w4.w, s);
    }
    #pragma unroll
    for (int off=16;off>0;off>>=1) s += __shfl_xor_sync(0xffffffffu,s,off);
    if (lane == 0) out[NER_TOTAL + bp] = s + b_r2[0];
}

// ============================================================================
extern "C" void kernel_launch(void* const* d_in, const int* in_sizes, int n_in,
                              void* d_out, int out_size)
{
    (void)in_sizes; (void)n_in; (void)out_size;
    const float* seq       = (const float*)d_in[0];
    const int*   span_start= (const int*)d_in[1];
    const int*   span_len  = (const int*)d_in[2];
    const int*   ent_type  = (const int*)d_in[3];
    const int*   pair_head = (const int*)d_in[4];
    const int*   pair_tail = (const int*)d_in[5];
    const int*   pair_rel  = (const int*)d_in[6];
    const float* W_ner1    = (const float*)d_in[7];
    const float* b_ner1    = (const float*)d_in[8];
    const float* W_ner2    = (const float*)d_in[9];
    const float* b_ner2    = (const float*)d_in[10];
    const float* type_emb  = (const float*)d_in[11];
    const float* W_g1      = (const float*)d_in[12];
    const float* a_src1    = (const float*)d_in[13];
    const float* a_dst1    = (const float*)d_in[14];
    const float* b_g1      = (const float*)d_in[15];
    const float* g1_gamma  = (const float*)d_in[16];
    const float* g1_beta   = (const float*)d_in[17];
    const float* W_g2      = (const float*)d_in[18];
    const float* a_src2    = (const float*)d_in[19];
    const float* a_dst2    = (const float*)d_in[20];
    const float* b_g2      = (const float*)d_in[21];
    const float* g2_gamma  = (const float*)d_in[22];
    const float* g2_beta   = (const float*)d_in[23];
    const float* rel_emb   = (const float*)d_in[24];
    const float* W_r1      = (const float*)d_in[25];
    const float* b_r1      = (const float*)d_in[26];
    const float* W_r2      = (const float*)d_in[27];
    const float* b_r2      = (const float*)d_in[28];
    float* out = (float*)d_out;

    static cudaStream_t sA = nullptr;
    static cudaEvent_t evRoot = nullptr, evT = nullptr, evA = nullptr;
    if (!sA){
        cudaStreamCreateWithFlags(&sA, cudaStreamNonBlocking);
        cudaEventCreateWithFlags(&evRoot, cudaEventDisableTiming);
        cudaEventCreateWithFlags(&evT, cudaEventDisableTiming);
        cudaEventCreateWithFlags(&evA, cudaEventDisableTiming);
    }

    uint4 *pSh, *pSl, *pXh, *pXl, *pW1h, *pW1l, *pG1h, *pG1l;
    cudaGetSymbolAddress((void**)&pSh,  g_pSh);
    cudaGetSymbolAddress((void**)&pSl,  g_pSl);
    cudaGetSymbolAddress((void**)&pXh,  g_pXh);
    cudaGetSymbolAddress((void**)&pXl,  g_pXl);
    cudaGetSymbolAddress((void**)&pW1h, g_pW1h);
    cudaGetSymbolAddress((void**)&pW1l, g_pW1l);
    cudaGetSymbolAddress((void**)&pG1h, g_pG1h);
    cudaGetSymbolAddress((void**)&pG1l, g_pG1l);
    float *xsrc;
    cudaGetSymbolAddress((void**)&xsrc, g_x);

    cudaFuncSetAttribute((const void*)pool_kernel,
                         cudaFuncAttributeMaxDynamicSharedMemorySize, 65536);
    cudaFuncSetAttribute((const void*)mma_merged,
                         cudaFuncAttributeMaxDynamicSharedMemorySize, 65536);

    // ---- fork: packs + cls/rp on side stream (record-before-wait only) ----
    cudaEventRecord(evRoot, 0);
    cudaStreamWaitEvent(sA, evRoot, 0);
    pack_b<<<96, 256, 0, sA>>>(W_ner1, 256, pW1h, pW1l);
    pack_b<<<192, 256, 0, sA>>>(W_g1, 512, pG1h, pG1l);
    pack_a<<<(1536*48)/8, 256, 0, sA>>>(seq, pSh, pSl);
    cudaEventRecord(evT, sA);
    cls_kernel<<<dim3(BB, 4), 256, 0, sA>>>(seq, W_r1, b_r1);
    rp_kernel<<<9, 256, 0, sA>>>(rel_emb, W_r1);
    cudaEventRecord(evA, sA);

    // ---- main chain ----
    pool_kernel<<<BB*EE, 256, LL*HH*sizeof(float)>>>(seq, span_start, span_len,
                                                     ent_type, type_emb);
    pack_a<<<(384*48)/8, 256>>>(xsrc, pXh, pXl);
    sim_kernel<<<BB*2, 128>>>();
    topk_kernel<<<(BB*EE)/8, 256>>>();

    cudaStreamWaitEvent(0, evT, 0);
    mma_merged<<<576, 256, 65536>>>(pSh, pSl, pW1h, pW1l,
                                    pXh, pXl, pG1h, pG1l, b_ner1);
    ner_head<<<(BB*SS)/8, 256>>>(W_ner2, b_ner2, out);
    sd1_kernel<<<BB*EE, 128>>>(a_src1, a_dst1);
    att1_kernel<<<BB*EE, 128>>>(b_g1, g1_gamma, g1_beta, W_g2, a_src2, a_dst2);
    att2_kernel<<<BB*EE, 128>>>(b_g2, g2_gamma, g2_beta);
    gemm_kernel<<<dim3((BB*EE)/64, 2, 2), 128>>>(W_r1, 256, 64);
    cudaStreamWaitEvent(0, evA, 0);
    pair_kernel<<<(BB*PP)/8, 256>>>(pair_head, pair_tail, pair_rel,
                                    W_r2, b_r2, out);
}

// round 17
// speedup vs baseline: 1.1212x; 1.1212x over previous
#include <cuda_runtime.h>
#include <cuda_bf16.h>
#include <cstdint>
#include <math.h>

#define BB 48
#define SS 512
#define HH 768
#define EE 128
#define LL 16
#define PP 256
#define NERC 11
#define NER_TOTAL (BB*SS*NERC)   // 270336

// ---------------- scratch (device globals; no allocation allowed) -------------
__device__ __align__(16) float g_x  [BB*EE*HH];
__device__ __align__(16) float g_xn [BB*EE*HH];
__device__ __align__(16) float g_sim[BB*EE*EE];
__device__ unsigned char g_Adj[BB*EE*EE];
__device__ __align__(16) float g_h1 [BB*EE*512];
__device__ float g_s1 [BB*EE*4];
__device__ float g_d1 [BB*EE*4];
__device__ __align__(16) float g_h2 [BB*EE*64];
__device__ float g_s2 [BB*EE];
__device__ float g_d2 [BB*EE];
__device__ __align__(16) float g_ent[BB*EE*64];
__device__ __align__(16) float g_clsp[BB*256];
__device__ __align__(16) float g_hid[BB*SS*256];
__device__ __align__(16) float g_He [BB*EE*256];
__device__ __align__(16) float g_Te [BB*EE*256];
__device__ __align__(16) float g_Rp [9*256];
// packed mma fragments: uint4 per (tile16, kchunk, lane)
__device__ uint4 g_pSh[1536*48*32];
__device__ uint4 g_pSl[1536*48*32];
__device__ uint4 g_pXh[384*48*32];
__device__ uint4 g_pXl[384*48*32];
__device__ uint4 g_pW1h[16*48*32];
__device__ uint4 g_pW1l[16*48*32];
__device__ uint4 g_pG1h[32*48*32];
__device__ uint4 g_pG1l[32*48*32];

// ---------------- helpers ----------------
__device__ __forceinline__ unsigned long long ffma2(unsigned long long a,
                                                    unsigned long long b,
                                                    unsigned long long c){
    unsigned long long d;
    asm("fma.rn.f32x2 %0, %1, %2, %3;" : "=l"(d) : "l"(a), "l"(b), "l"(c));
    return d;
}
union F2U { unsigned long long u; float2 f; };
__device__ __forceinline__ void cpa16(void* s, const void* g){
    unsigned sa = (unsigned)__cvta_generic_to_shared(s);
    asm volatile("cp.async.ca.shared.global [%0], [%1], 16;" :: "r"(sa), "l"(g));
}
__device__ __forceinline__ void mma16816(float* c, const unsigned* a, const unsigned* b){
    asm volatile("mma.sync.aligned.m16n8k16.row.col.f32.bf16.bf16.f32 "
        "{%0,%1,%2,%3}, {%4,%5,%6,%7}, {%8,%9}, {%0,%1,%2,%3};"
        : "+f"(c[0]), "+f"(c[1]), "+f"(c[2]), "+f"(c[3])
        : "r"(a[0]), "r"(a[1]), "r"(a[2]), "r"(a[3]), "r"(b[0]), "r"(b[1]));
}
__device__ __forceinline__ void bsplit2(float x, float y, unsigned& h, unsigned& l){
    __nv_bfloat16 hx = __float2bfloat16(x);
    __nv_bfloat16 hy = __float2bfloat16(y);
    __nv_bfloat16 lx = __float2bfloat16(x - __bfloat162float(hx));
    __nv_bfloat16 ly = __float2bfloat16(y - __bfloat162float(hy));
    unsigned short ux = *(unsigned short*)&hx, uy = *(unsigned short*)&hy;
    unsigned short vx = *(unsigned short*)&lx, vy = *(unsigned short*)&ly;
    h = (unsigned)ux | ((unsigned)uy << 16);
    l = (unsigned)vx | ((unsigned)vy << 16);
}

// ============================================================================
// pack_a: fp32 A[M,768] -> packed fragment uint4 arrays (hi, lo).
// ============================================================================
__global__ __launch_bounds__(256) void pack_a(const float* __restrict__ A,
                                              uint4* __restrict__ oh,
                                              uint4* __restrict__ ol)
{
    int unit = blockIdx.x*8 + (threadIdx.x >> 5);
    int lane = threadIdx.x & 31;
    int tile = unit / 48, c = unit % 48;
    int g = lane >> 2, tg = lane & 3;
    const float* base = A + (size_t)tile*16*HH + c*16;
    float2 r0 = *(const float2*)(base + (size_t)g*HH + tg*2);
    float2 r1 = *(const float2*)(base + (size_t)(g+8)*HH + tg*2);
    float2 r2 = *(const float2*)(base + (size_t)g*HH + 8 + tg*2);
    float2 r3 = *(const float2*)(base + (size_t)(g+8)*HH + 8 + tg*2);
    uint4 H, L;
    bsplit2(r0.x, r0.y, H.x, L.x);
    bsplit2(r1.x, r1.y, H.y, L.y);
    bsplit2(r2.x, r2.y, H.z, L.z);
    bsplit2(r3.x, r3.y, H.w, L.w);
    size_t o = (size_t)unit*32 + lane;
    oh[o] = H; ol[o] = L;
}

// ============================================================================
// pack_b: fp32 W[768,N] (k-major) -> transposed packed B fragments.
// ============================================================================
__global__ __launch_bounds__(256) void pack_b(const float* __restrict__ W, int N,
                                              uint4* __restrict__ oh,
                                              uint4* __restrict__ ol)
{
    int unit = blockIdx.x*8 + (threadIdx.x >> 5);
    int lane = threadIdx.x & 31;
    int nt = unit / 48, c = unit % 48;
    int g = lane >> 2, tg = lane & 3;
    const float* p = W + (size_t)(c*16)*N + nt*16;
    float x0 = p[(tg*2)*N + g],       x1 = p[(tg*2+1)*N + g];
    float x2 = p[(8+tg*2)*N + g],     x3 = p[(8+tg*2+1)*N + g];
    float x4 = p[(tg*2)*N + g+8],     x5 = p[(tg*2+1)*N + g+8];
    float x6 = p[(8+tg*2)*N + g+8],   x7 = p[(8+tg*2+1)*N + g+8];
    uint4 H, L;
    bsplit2(x0, x1, H.x, L.x);
    bsplit2(x2, x3, H.y, L.y);
    bsplit2(x4, x5, H.z, L.z);
    bsplit2(x6, x7, H.w, L.w);
    size_t o = (size_t)unit*32 + lane;
    oh[o] = H; ol[o] = L;
}

// ============================================================================
// mma_merged: both big GEMMs in one launch (576 tiles of 128x128x768).
// bid < 384: NER (hid = relu(seq@W1+b1));  bid >= 384: gat1 (h1 = x@Wg1),
// with sd1 (s1/d1 head dots) FUSED into the gat1 epilogue.
// ============================================================================
__global__ __launch_bounds__(256, 2) void mma_merged(
    const uint4* __restrict__ Sh, const uint4* __restrict__ Sl,
    const uint4* __restrict__ W1h, const uint4* __restrict__ W1l,
    const uint4* __restrict__ Xh, const uint4* __restrict__ Xl,
    const uint4* __restrict__ G1h, const uint4* __restrict__ G1l,
    const float* __restrict__ b_ner1,
    const float* __restrict__ a_src1, const float* __restrict__ a_dst1)
{
    extern __shared__ __align__(16) uint4 sm4[];   // 4 slots x 1024 uint4 = 64KB
    int bid = blockIdx.x;
    int tid = threadIdx.x, lane = tid & 31, wid = tid >> 5;
    int wm = wid & 3, wn = wid >> 2;
    int g = lane >> 2, tg = lane & 3;

    const uint4 *Ah, *Al, *Bh, *Bl;
    float* C; const float* bias;
    int N, m0, n0, dorelu;
    if (bid < 384){
        m0 = (bid >> 1)*128; n0 = (bid & 1)*128;
        Ah = Sh; Al = Sl; Bh = W1h; Bl = W1l;
        C = g_hid; N = 256; bias = b_ner1; dorelu = 1;
    } else {
        int b2 = bid - 384;
        m0 = (b2 >> 2)*128; n0 = (b2 & 3)*128;
        Ah = Xh; Al = Xl; Bh = G1h; Bl = G1l;
        C = g_h1; N = 512; bias = nullptr; dorelu = 0;
    }

    float acc[2][8][4];
    #pragma unroll
    for (int mt=0;mt<2;mt++)
        #pragma unroll
        for (int nt=0;nt<8;nt++)
            #pragma unroll
            for (int q=0;q<4;q++) acc[mt][nt][q] = 0.f;

    const uint4* srcs[4];
    int dsti[4];
    #pragma unroll
    for (int q=0;q<4;q++){
        int idx = tid + 256*q;
        int seg = idx >> 5, l2 = idx & 31;
        int t = seg & 7;
        const uint4* base;
        size_t ub;
        if (seg < 8)       { base = Ah; ub = (size_t)((m0>>4)+t)*48*32; }
        else if (seg < 16) { base = Al; ub = (size_t)((m0>>4)+t)*48*32; }
        else if (seg < 24) { base = Bh; ub = (size_t)((n0>>4)+t)*48*32; }
        else               { base = Bl; ub = (size_t)((n0>>4)+t)*48*32; }
        srcs[q] = base + ub + l2;
        dsti[q] = idx;
    }

    #pragma unroll
    for (int s=0; s<3; s++){
        #pragma unroll
        for (int q=0;q<4;q++)
            cpa16(&sm4[s*1024 + dsti[q]], srcs[q] + s*32);
        asm volatile("cp.async.commit_group;");
    }

    for (int c = 0; c < 48; c++){
        asm volatile("cp.async.wait_group 2;");
        __syncthreads();
        if (c + 3 < 48){
            #pragma unroll
            for (int q=0;q<4;q++)
                cpa16(&sm4[((c+3)&3)*1024 + dsti[q]], srcs[q] + (c+3)*32);
        }
        asm volatile("cp.async.commit_group;");

        const uint4* slot = &sm4[(c & 3)*1024];
        uint4 b4H[4], b4L[4];
        #pragma unroll
        for (int j=0;j<4;j++){
            b4H[j] = slot[(16 + wn*4 + j)*32 + lane];
            b4L[j] = slot[(24 + wn*4 + j)*32 + lane];
        }
        #pragma unroll
        for (int mt=0; mt<2; mt++){
            uint4 a4H = slot[(wm*2 + mt)*32 + lane];
            uint4 a4L = slot[(8 + wm*2 + mt)*32 + lane];
            unsigned aH[4] = {a4H.x, a4H.y, a4H.z, a4H.w};
            unsigned aL[4] = {a4L.x, a4L.y, a4L.z, a4L.w};
            #pragma unroll
            for (int j=0; j<4; j++){
                unsigned bHe[2] = {b4H[j].x, b4H[j].y};
                unsigned bHo[2] = {b4H[j].z, b4H[j].w};
                unsigned bLe[2] = {b4L[j].x, b4L[j].y};
                unsigned bLo[2] = {b4L[j].z, b4L[j].w};
                mma16816(acc[mt][2*j],   aH, bHe);
                mma16816(acc[mt][2*j],   aH, bLe);
                mma16816(acc[mt][2*j],   aL, bHe);
                mma16816(acc[mt][2*j+1], aH, bHo);
                mma16816(acc[mt][2*j+1], aH, bLo);
                mma16816(acc[mt][2*j+1], aL, bHo);
            }
        }
    }

    // ---- C store epilogue ----
    #pragma unroll
    for (int mt=0; mt<2; mt++){
        int rbase = m0 + wm*32 + mt*16 + g;
        #pragma unroll
        for (int nt=0; nt<8; nt++){
            int col = n0 + wn*64 + nt*8 + tg*2;
            float b0 = 0.f, b1 = 0.f;
            if (bias){ b0 = bias[col]; b1 = bias[col+1]; }
            float v0 = acc[mt][nt][0] + b0, v1 = acc[mt][nt][1] + b1;
            float v2 = acc[mt][nt][2] + b0, v3 = acc[mt][nt][3] + b1;
            if (dorelu){
                v0 = fmaxf(v0,0.f); v1 = fmaxf(v1,0.f);
                v2 = fmaxf(v2,0.f); v3 = fmaxf(v3,0.f);
            }
            *(float2*)&C[(size_t)rbase*N + col]     = make_float2(v0, v1);
            *(float2*)&C[(size_t)(rbase+8)*N + col] = make_float2(v2, v3);
        }
    }

    // ---- fused sd1 epilogue (gat1 tiles only; bid uniform per block) ----
    if (bid >= 384){
        __syncthreads();                    // pipeline smem dead; repurpose
        float* fsm = (float*)sm4;           // [0,256): s parts, [256,512): d parts

        float sacc[4] = {0.f,0.f,0.f,0.f};
        float dacc[4] = {0.f,0.f,0.f,0.f};
        #pragma unroll
        for (int nt=0; nt<8; nt++){
            int col = n0 + wn*64 + nt*8 + tg*2;   // global within 512 = a_src index
            float as0 = a_src1[col], as1 = a_src1[col+1];
            float ad0 = a_dst1[col], ad1 = a_dst1[col+1];
            #pragma unroll
            for (int mt=0; mt<2; mt++){
                sacc[mt*2]   = fmaf(acc[mt][nt][0], as0, fmaf(acc[mt][nt][1], as1, sacc[mt*2]));
                sacc[mt*2+1] = fmaf(acc[mt][nt][2], as0, fmaf(acc[mt][nt][3], as1, sacc[mt*2+1]));
                dacc[mt*2]   = fmaf(acc[mt][nt][0], ad0, fmaf(acc[mt][nt][1], ad1, dacc[mt*2]));
                dacc[mt*2+1] = fmaf(acc[mt][nt][2], ad0, fmaf(acc[mt][nt][3], ad1, dacc[mt*2+1]));
            }
        }
        #pragma unroll
        for (int r4=0; r4<4; r4++){
            sacc[r4] += __shfl_xor_sync(0xffffffffu, sacc[r4], 1);
            sacc[r4] += __shfl_xor_sync(0xffffffffu, sacc[r4], 2);
            dacc[r4] += __shfl_xor_sync(0xffffffffu, dacc[r4], 1);
            dacc[r4] += __shfl_xor_sync(0xffffffffu, dacc[r4], 2);
        }
        if (tg == 0){
            #pragma unroll
            for (int r4=0; r4<4; r4++){
                int mt = r4 >> 1, half = r4 & 1;
                int r = wm*32 + mt*16 + half*8 + g;
                fsm[wn*128 + r]       = sacc[r4];
                fsm[256 + wn*128 + r] = dacc[r4];
            }
        }
        __syncthreads();
        if (tid < 128){
            int hd = n0 >> 7;
            g_s1[(size_t)(m0 + tid)*4 + hd] = fsm[tid] + fsm[128 + tid];
            g_d1[(size_t)(m0 + tid)*4 + hd] = fsm[256 + tid] + fsm[384 + tid];
        }
    }
}

// ============================================================================
// Small-GEMM (He/Te merged): FFMA2, 64x128 tile; blockIdx.z picks He vs Te.
// ============================================================================
__global__ __launch_bounds__(128, 3) void gemm_kernel(
    const float* __restrict__ Bbase, int ldb, int K)
{
    __shared__ __align__(16) float2 As2[2][16][64];
    __shared__ __align__(16) float  Bs [2][16][128];

    const float* A = g_ent;
    const float* B = Bbase + (size_t)blockIdx.z * 64 * 256;
    float* C = blockIdx.z ? g_Te : g_He;

    int tid = threadIdx.x;
    int tm = tid >> 4, tn = tid & 15;
    int m0 = blockIdx.x * 64, n0 = blockIdx.y * 128;
    int nch = K >> 4;

    unsigned long long acc[8][4];
    #pragma unroll
    for (int i=0;i<8;i++)
        #pragma unroll
        for (int p=0;p<4;p++) acc[i][p] = 0ull;

    int lr = tid >> 1, lc8 = (tid & 1) * 8;
    const float* aP = A + (size_t)(m0 + lr) * K + lc8;
    int bkk[4], bc4[4];
    #pragma unroll
    for (int i=0;i<4;i++){ int q = i*128 + tid; bkk[i] = q >> 5; bc4[i] = (q & 31) * 4; }

    float4 pa0, pa1;
    pa0 = *(const float4*)(aP);
    pa1 = *(const float4*)(aP + 4);
    #pragma unroll
    for (int i=0;i<4;i++)
        cpa16(&Bs[0][bkk[i]][bc4[i]], B + (size_t)bkk[i]*ldb + n0 + bc4[i]);
    asm volatile("cp.async.commit_group;");
    {
        float v[8] = {pa0.x,pa0.y,pa0.z,pa0.w,pa1.x,pa1.y,pa1.z,pa1.w};
        #pragma unroll
        for (int j=0;j<8;j++) As2[0][lc8+j][lr] = make_float2(v[j],v[j]);
    }

    for (int c = 0; c < nch; c++){
        int cb = c & 1, nb = cb ^ 1;
        if (c + 1 < nch){
            int k0n = (c+1)*16;
            pa0 = *(const float4*)(aP + k0n);
            pa1 = *(const float4*)(aP + k0n + 4);
            #pragma unroll
            for (int i=0;i<4;i++)
                cpa16(&Bs[nb][bkk[i]][bc4[i]],
                      B + (size_t)(k0n + bkk[i])*ldb + n0 + bc4[i]);
            asm volatile("cp.async.commit_group;");
            asm volatile("cp.async.wait_group 1;");
        } else {
            asm volatile("cp.async.wait_group 0;");
        }
        __syncthreads();
        #pragma unroll
        for (int kk=0;kk<16;kk++){
            unsigned long long b2[4];
            #pragma unroll
            for (int p=0;p<4;p++)
                b2[p] = *(const unsigned long long*)&Bs[cb][kk][2*(tn + 16*p)];
            #pragma unroll
            for (int i=0;i<8;i++){
                unsigned long long a2 =
                    *(const unsigned long long*)&As2[cb][kk][tm*8+i];
                acc[i][0] = ffma2(a2, b2[0], acc[i][0]);
                acc[i][1] = ffma2(a2, b2[1], acc[i][1]);
                acc[i][2] = ffma2(a2, b2[2], acc[i][2]);
                acc[i][3] = ffma2(a2, b2[3], acc[i][3]);
            }
        }
        __syncthreads();
        if (c + 1 < nch){
            float v[8] = {pa0.x,pa0.y,pa0.z,pa0.w,pa1.x,pa1.y,pa1.z,pa1.w};
            #pragma unroll
            for (int j=0;j<8;j++) As2[nb][lc8+j][lr] = make_float2(v[j],v[j]);
        }
    }

    #pragma unroll
    for (int i=0;i<8;i++){
        size_t row = m0 + tm*8 + i;
        #pragma unroll
        for (int p=0;p<4;p++){
            F2U u; u.u = acc[i][p];
            *(float2*)&C[row*ldb + n0 + 32*p + 2*tn] = u.f;
        }
    }
}

// ============================================================================
// ner_head: out = g_hid @ W2 + b2.
// ============================================================================
__global__ __launch_bounds__(256) void ner_head(
    const float* __restrict__ W2, const float* __restrict__ b2,
    float* __restrict__ out)
{
    __shared__ float W2t[NERC][256];
    __shared__ float b2s[NERC];
    int tid = threadIdx.x;
    for (int i = tid; i < 256*NERC; i += 256){
        int c = i / NERC, jo = i % NERC;
        W2t[jo][c] = W2[i];
    }
    if (tid < NERC) b2s[tid] = b2[tid];
    __syncthreads();
    int w = tid >> 5, lane = tid & 31;
    int row = blockIdx.x*8 + w;
    const float* hr = &g_hid[(size_t)row*256 + lane*8];
    float4 v0 = *(const float4*)hr;
    float4 v1 = *(const float4*)(hr + 4);
    #pragma unroll
    for (int jo = 0; jo < NERC; jo++){
        const float* wr = &W2t[jo][lane*8];
        float4 w0 = *(const float4*)wr;
        float4 w1 = *(const float4*)(wr + 4);
        float p = 0.f;
        p = fmaf(v0.x, w0.x, p); p = fmaf(v0.y, w0.y, p);
        p = fmaf(v0.z, w0.z, p); p = fmaf(v0.w, w0.w, p);
        p = fmaf(v1.x, w1.x, p); p = fmaf(v1.y, w1.y, p);
        p = fmaf(v1.z, w1.z, p); p = fmaf(v1.w, w1.w, p);
        #pragma unroll
        for (int off=16;off>0;off>>=1) p += __shfl_xor_sync(0xffffffffu,p,off);
        if (lane == 0) out[row*NERC + jo] = p + b2s[jo];
    }
}

// ============================================================================
// pool_kernel: loads only len+1 token rows.
// ============================================================================
__global__ __launch_bounds__(256) void pool_kernel(
    const float* __restrict__ seq, const int* __restrict__ span_start,
    const int* __restrict__ span_len, const int* __restrict__ ent_type,
    const float* __restrict__ type_emb)
{
    extern __shared__ float tok[];
    __shared__ float meanv[HH];
    __shared__ float sc[LL];
    __shared__ float wv[LL];
    __shared__ float red[8];

    int be = blockIdx.x;
    int b = be / EE;
    int tid = threadIdx.x;
    int start = span_start[be];
    int len = span_len[be];
    float cnt = (float)(len + 1);

    const float4* src = (const float4*)&seq[(size_t)(b*SS + start)*HH];
    float4* dst4 = (float4*)tok;
    int nv4 = (len + 1) * (HH/4);
    for (int q = tid; q < nv4; q += 256) dst4[q] = src[q];
    __syncthreads();

    for (int d = tid; d < HH; d += 256){
        float s = 0.f;
        for (int l = 0; l <= len; l++) s += tok[l*HH + d];
        meanv[d] = s / cnt;
    }
    __syncthreads();

    int w = tid >> 5, lane = tid & 31;
    for (int l = w; l <= len; l += 8){
        float p = 0.f;
        for (int d = lane; d < HH; d += 32) p = fmaf(tok[l*HH+d], meanv[d], p);
        #pragma unroll
        for (int off=16;off>0;off>>=1) p += __shfl_xor_sync(0xffffffffu,p,off);
        if (lane==0) sc[l] = p;
    }
    __syncthreads();

    if (tid == 0){
        float mx = -1e30f;
        for (int l=0;l<=len;l++) mx = fmaxf(mx, sc[l]);
        float s = 0.f;
        for (int l=0;l<=len;l++){ float e = expf(sc[l]-mx); wv[l]=e; s+=e; }
        float inv = 1.f/s;
        for (int l=0;l<=len;l++) wv[l] *= inv;
        for (int l=len+1;l<LL;l++) wv[l] = 0.f;
    }
    __syncthreads();

    const float* te = &type_emb[ent_type[be]*HH];
    float xv[3]; float nsq = 0.f;
    #pragma unroll
    for (int q = 0; q < 3; q++){
        int d = tid + q*256;
        float p = 0.f;
        for (int l = 0; l <= len; l++) p = fmaf(wv[l], tok[l*HH+d], p);
        float v = p + te[d];
        xv[q] = v;
        g_x[(size_t)be*HH + d] = v;
        nsq = fmaf(v, v, nsq);
    }
    #pragma unroll
    for (int off=16;off>0;off>>=1) nsq += __shfl_xor_sync(0xffffffffu,nsq,off);
    if (lane==0) red[w] = nsq;
    __syncthreads();
    float tot = 0.f;
    #pragma unroll
    for (int i=0;i<8;i++) tot += red[i];
    float inv = 1.f / fmaxf(sqrtf(tot), 1e-12f);
    #pragma unroll
    for (int q=0;q<3;q++){
        int d = tid + q*256;
        g_xn[(size_t)be*HH + d] = xv[q]*inv;
    }
}

// ============================================================================
// sim_kernel (FFMA2)
// ============================================================================
__global__ __launch_bounds__(128) void sim_kernel()
{
    __shared__ __align__(16) float2 As2[2][16][64];
    __shared__ float Xt[2][16][132];

    int b = blockIdx.x >> 1;
    int i0 = (blockIdx.x & 1) * 64;
    const float* X = &g_xn[(size_t)b*EE*HH];
    int tid = threadIdx.x;
    int tm = tid >> 4, tn = tid & 15;

    unsigned long long acc[8][4];
    #pragma unroll
    for (int i=0;i<8;i++)
        #pragma unroll
        for (int p=0;p<4;p++) acc[i][p] = 0ull;

    int ar = tid >> 1, akq = (tid & 1) * 8;
    const float* aP = X + (size_t)(i0 + ar)*HH + akq;
    const float* xP = X + (size_t)tid*HH;

    float4 pa0, pa1, px[4];
    pa0 = *(const float4*)(aP);
    pa1 = *(const float4*)(aP + 4);
    #pragma unroll
    for (int q=0;q<4;q++) px[q] = *(const float4*)(xP + 4*q);
    {
        float v[8] = {pa0.x,pa0.y,pa0.z,pa0.w,pa1.x,pa1.y,pa1.z,pa1.w};
        #pragma unroll
        for (int j=0;j<8;j++) As2[0][akq+j][ar] = make_float2(v[j],v[j]);
        #pragma unroll
        for (int q=0;q<4;q++){
            Xt[0][4*q+0][tid] = px[q].x;
            Xt[0][4*q+1][tid] = px[q].y;
            Xt[0][4*q+2][tid] = px[q].z;
            Xt[0][4*q+3][tid] = px[q].w;
        }
    }

    for (int c = 0; c < 48; c++){
        int cb = c & 1, nb = cb ^ 1;
        __syncthreads();
        if (c + 1 < 48){
            int k0n = (c+1)*16;
            pa0 = *(const float4*)(aP + k0n);
            pa1 = *(const float4*)(aP + k0n + 4);
            #pragma unroll
            for (int q=0;q<4;q++) px[q] = *(const float4*)(xP + k0n + 4*q);
        }
        #pragma unroll
        for (int kk=0;kk<16;kk++){
            unsigned long long b2[4];
            #pragma unroll
            for (int p=0;p<4;p++)
                b2[p] = *(const unsigned long long*)&Xt[cb][kk][2*(tn + 16*p)];
            #pragma unroll
            for (int i=0;i<8;i++){
                unsigned long long a2 =
                    *(const unsigned long long*)&As2[cb][kk][tm*8+i];
                acc[i][0] = ffma2(a2, b2[0], acc[i][0]);
                acc[i][1] = ffma2(a2, b2[1], acc[i][1]);
                acc[i][2] = ffma2(a2, b2[2], acc[i][2]);
                acc[i][3] = ffma2(a2, b2[3], acc[i][3]);
            }
        }
        if (c + 1 < 48){
            float v[8] = {pa0.x,pa0.y,pa0.z,pa0.w,pa1.x,pa1.y,pa1.z,pa1.w};
            #pragma unroll
            for (int j=0;j<8;j++) As2[nb][akq+j][ar] = make_float2(v[j],v[j]);
            #pragma unroll
            for (int q=0;q<4;q++){
                Xt[nb][4*q+0][tid] = px[q].x;
                Xt[nb][4*q+1][tid] = px[q].y;
                Xt[nb][4*q+2][tid] = px[q].z;
                Xt[nb][4*q+3][tid] = px[q].w;
            }
        }
    }

    float* simb = &g_sim[(size_t)b*EE*EE];
    #pragma unroll
    for (int i=0;i<8;i++){
        int row = i0 + tm*8 + i;
        #pragma unroll
        for (int p=0;p<4;p++){
            F2U u; u.u = acc[i][p];
            *(float2*)&simb[row*EE + 2*(tn + 16*p)] = u.f;
        }
    }
}

// ============================================================================
// topk_kernel
// ============================================================================
__global__ __launch_bounds__(256) void topk_kernel()
{
    int w = threadIdx.x >> 5, lane = threadIdx.x & 31;
    int row = blockIdx.x*8 + w;
    int i = row & 127;
    const float* r = &g_sim[(size_t)row*EE];
    float v[4];
    #pragma unroll
    for (int q=0;q<4;q++) v[q] = r[lane + q*32];
    unsigned used = 0;
    int pick[6]; float pval[6];
    for (int k=0;k<6;k++){
        float bv = -1e30f; int bj = 128;
        #pragma unroll
        for (int q=0;q<4;q++){
            if (!((used>>q)&1u)){
                int j = lane + q*32;
                if (v[q] > bv){ bv = v[q]; bj = j; }
            }
        }
        #pragma unroll
        for (int off=16; off>0; off>>=1){
            float ov = __shfl_xor_sync(0xffffffffu, bv, off);
            int   oj = __shfl_xor_sync(0xffffffffu, bj, off);
            if (ov > bv || (ov == bv && oj < bj)){ bv = ov; bj = oj; }
        }
        pick[k]=bj; pval[k]=bv;
        if ((bj & 31) == lane) used |= 1u << (bj >> 5);
    }
    int jb = lane*4;
    unsigned char c0=0,c1=0,c2=0,c3=0;
    #pragma unroll
    for (int k=0;k<6;k++){
        if (pval[k] > 0.1f && pick[k] != i){
            int d = pick[k] - jb;
            if (d==0) c0=1; else if (d==1) c1=1; else if (d==2) c2=1; else if (d==3) c3=1;
        }
    }
    int ds = i - jb;
    if (ds>=0 && ds<4){ if(ds==0)c0=1; else if(ds==1)c1=1; else if(ds==2)c2=1; else c3=1; }
    *(uchar4*)&g_Adj[(size_t)row*EE + jb] = make_uchar4(c0,c1,c2,c3);
}

// ============================================================================
// att1_kernel (FUSED with gat2h): computes g1v row in smem, then
// h2 = g1v @ W_g2 (512->64) + s2/d2 dots, all in one block per (b,t).
// ============================================================================
__global__ __launch_bounds__(128) void att1_kernel(
    const float* __restrict__ b_g1, const float* __restrict__ gamma,
    const float* __restrict__ beta, const float* __restrict__ Wg2,
    const float* __restrict__ a_src2, const float* __restrict__ a_dst2)
{
    __shared__ int act[EE];
    __shared__ int wcnt[4], woff[4];
    __shared__ int nact_s;
    __shared__ float wts[4][EE];
    __shared__ float red[4], red2[4];
    __shared__ float ysm[512];
    __shared__ float part2[2][64];
    __shared__ float rs[2], rd[2];

    int be = blockIdx.x;
    int b = be / EE, t = be % EE;
    int tid = threadIdx.x, w = tid>>5, lane = tid&31;

    bool flag = g_Adj[(size_t)(b*EE + tid)*EE + t] != 0;
    unsigned mball = __ballot_sync(0xffffffffu, flag);
    if (lane==0) wcnt[w] = __popc(mball);
    __syncthreads();
    if (tid==0){ int o=0; for (int i2=0;i2<4;i2++){ woff[i2]=o; o+=wcnt[i2]; } nact_s=o; }
    __syncthreads();
    if (flag) act[woff[w] + __popc(mball & ((1u<<lane)-1u))] = tid;
    __syncthreads();
    int nact = nact_s;

    {
        int hd = w;
        float dv = g_d1[be*4 + hd];
        float mx = -1e30f;
        for (int k=lane;k<nact;k+=32){
            float e = g_s1[(b*EE+act[k])*4 + hd] + dv;
            e = e > 0.f ? e : 0.2f*e;
            wts[hd][k] = e;
            mx = fmaxf(mx, e);
        }
        #pragma unroll
        for (int off=16;off>0;off>>=1) mx = fmaxf(mx, __shfl_xor_sync(0xffffffffu,mx,off));
        float sum = 0.f;
        for (int k=lane;k<nact;k+=32){
            float e = expf(wts[hd][k]-mx);
            wts[hd][k] = e; sum += e;
        }
        #pragma unroll
        for (int off=16;off>0;off>>=1) sum += __shfl_xor_sync(0xffffffffu,sum,off);
        float inv = 1.f/sum;
        for (int k=lane;k<nact;k+=32) wts[hd][k] *= inv;
    }
    __syncthreads();

    float ov[4];
    #pragma unroll
    for (int q=0;q<4;q++){
        int f = tid + q*128;
        float o = 0.f;
        for (int k=0;k<nact;k++)
            o = fmaf(wts[q][k], g_h1[(size_t)(b*EE+act[k])*512 + f], o);
        ov[q] = o + b_g1[f];
    }
    float ls = ov[0]+ov[1]+ov[2]+ov[3];
    #pragma unroll
    for (int off=16;off>0;off>>=1) ls += __shfl_xor_sync(0xffffffffu,ls,off);
    if (lane==0) red[w] = ls;
    __syncthreads();
    float mean = (red[0]+red[1]+red[2]+red[3]) * (1.f/512.f);
    float lv = 0.f;
    #pragma unroll
    for (int q=0;q<4;q++){ float d = ov[q]-mean; lv = fmaf(d,d,lv); }
    #pragma unroll
    for (int off=16;off>0;off>>=1) lv += __shfl_xor_sync(0xffffffffu,lv,off);
    if (lane==0) red2[w] = lv;
    __syncthreads();
    float var = (red2[0]+red2[1]+red2[2]+red2[3]) * (1.f/512.f);
    float rstd = rsqrtf(var + 1e-5f);
    #pragma unroll
    for (int q=0;q<4;q++){
        int f = tid + q*128;
        float y = (ov[q]-mean)*rstd*gamma[f] + beta[f];
        y = y > 0.f ? y : expm1f(y);
        ysm[f] = y;
    }
    __syncthreads();

    {
        int col = tid & 63, half = tid >> 6;
        const float* wp = &Wg2[(size_t)(half*256)*64 + col];
        const float* yp = &ysm[half*256];
        float a0=0.f, a1=0.f, a2=0.f, a3=0.f;
        #pragma unroll 4
        for (int k = 0; k < 256; k += 4){
            a0 = fmaf(yp[k],   wp[(size_t)k*64],     a0);
            a1 = fmaf(yp[k+1], wp[(size_t)(k+1)*64], a1);
            a2 = fmaf(yp[k+2], wp[(size_t)(k+2)*64], a2);
            a3 = fmaf(yp[k+3], wp[(size_t)(k+3)*64], a3);
        }
        part2[half][col] = (a0+a1)+(a2+a3);
    }
    __syncthreads();
    if (tid < 64){
        float a = part2[0][tid] + part2[1][tid];
        g_h2[(size_t)be*64 + tid] = a;
        float ps = a * a_src2[tid];
        float pd = a * a_dst2[tid];
        #pragma unroll
        for (int off=16;off>0;off>>=1){
            ps += __shfl_xor_sync(0xffffffffu,ps,off);
            pd += __shfl_xor_sync(0xffffffffu,pd,off);
        }
        if ((tid & 31) == 0){ rs[tid>>5] = ps; rd[tid>>5] = pd; }
    }
    __syncthreads();
    if (tid == 0){ g_s2[be] = rs[0]+rs[1]; g_d2[be] = rd[0]+rd[1]; }
}

// ============================================================================
// att2_kernel
// ============================================================================
__global__ __launch_bounds__(128) void att2_kernel(
    const float* __restrict__ b_g2, const float* __restrict__ gamma,
    const float* __restrict__ beta)
{
    __shared__ int act[EE];
    __shared__ int wcnt[4], woff[4];
    __shared__ int nact_s;
    __shared__ float wts[EE];
    __shared__ float red[2], red2[2];

    int be = blockIdx.x;
    int b = be / EE, t = be % EE;
    int tid = threadIdx.x, w = tid>>5, lane = tid&31;

    bool flag = g_Adj[(size_t)(b*EE + tid)*EE + t] != 0;
    unsigned mball = __ballot_sync(0xffffffffu, flag);
    if (lane==0) wcnt[w] = __popc(mball);
    __syncthreads();
    if (tid==0){ int o=0; for (int i2=0;i2<4;i2++){ woff[i2]=o; o+=wcnt[i2]; } nact_s=o; }
    __syncthreads();
    if (flag) act[woff[w] + __popc(mball & ((1u<<lane)-1u))] = tid;
    __syncthreads();
    int nact = nact_s;

    if (w == 0){
        float dv = g_d2[be];
        float mx = -1e30f;
        for (int k=lane;k<nact;k+=32){
            float e = g_s2[b*EE + act[k]] + dv;
            e = e > 0.f ? e : 0.2f*e;
            wts[k] = e;
            mx = fmaxf(mx, e);
        }
        #pragma unroll
        for (int off=16;off>0;off>>=1) mx = fmaxf(mx, __shfl_xor_sync(0xffffffffu,mx,off));
        float sum = 0.f;
        for (int k=lane;k<nact;k+=32){
            float e = expf(wts[k]-mx);
            wts[k] = e; sum += e;
        }
        #pragma unroll
        for (int off=16;off>0;off>>=1) sum += __shfl_xor_sync(0xffffffffu,sum,off);
        float inv = 1.f/sum;
        for (int k=lane;k<nact;k+=32) wts[k] *= inv;
    }
    __syncthreads();

    float o = 0.f;
    if (tid < 64){
        for (int k=0;k<nact;k++)
            o = fmaf(wts[k], g_h2[(size_t)(b*EE+act[k])*64 + tid], o);
        o += b_g2[tid];
    }
    float ls = (tid<64) ? o : 0.f;
    #pragma unroll
    for (int off=16;off>0;off>>=1) ls += __shfl_xor_sync(0xffffffffu,ls,off);
    if (w < 2 && lane==0) red[w] = ls;
    __syncthreads();
    float mean = (red[0]+red[1]) * (1.f/64.f);
    float dv2 = (tid<64) ? (o-mean) : 0.f;
    float lv = dv2*dv2;
    #pragma unroll
    for (int off=16;off>0;off>>=1) lv += __shfl_xor_sync(0xffffffffu,lv,off);
    if (w < 2 && lane==0) red2[w] = lv;
    __syncthreads();
    float var = (red2[0]+red2[1]) * (1.f/64.f);
    if (tid < 64){
        float y = (o-mean)*rsqrtf(var+1e-5f)*gamma[tid] + beta[tid];
        y = y > 0.f ? y : expm1f(y);
        g_ent[(size_t)be*64 + tid] = y;
    }
}

// ============================================================================
// cls_kernel v2: grid (48, 4); 256 thr = 64 cols x 4 kgroups; smem reduce.
// ============================================================================
__global__ __launch_bounds__(256) void cls_kernel(const float* __restrict__ seq,
                                                  const float* __restrict__ W_r1,
                                                  const float* __restrict__ b_r1)
{
    __shared__ float c[HH];
    __shared__ float part[4][64];
    int b = blockIdx.x, cq = blockIdx.y;
    int tid = threadIdx.x;
    int col = cq*64 + (tid & 63);
    int kg = tid >> 6;
    for (int d = tid; d < HH; d += 256) c[d] = seq[(size_t)b*SS*HH + d];
    __syncthreads();
    float acc = 0.f;
    const float* wp = &W_r1[(size_t)(160 + kg*192)*256 + col];
    #pragma unroll 4
    for (int d = 0; d < 192; d++)
        acc = fmaf(c[kg*192 + d], wp[(size_t)d*256], acc);
    part[kg][tid & 63] = acc;
    __syncthreads();
    if (tid < 64){
        float s = part[0][tid] + part[1][tid] + part[2][tid] + part[3][tid];
        g_clsp[b*256 + col] = s + b_r1[col];
    }
}

__global__ __launch_bounds__(256) void rp_kernel(const float* __restrict__ rel_emb,
                                                 const float* __restrict__ W_r1)
{
    __shared__ float re[32];
    int r = blockIdx.x, tid = threadIdx.x;
    if (tid < 32) re[tid] = rel_emb[r*32 + tid];
    __syncthreads();
    float s = 0.f;
    #pragma unroll 8
    for (int k=0;k<32;k++) s = fmaf(re[k], W_r1[(128+k)*256 + tid], s);
    g_Rp[r*256 + tid] = s;
}

__global__ __launch_bounds__(256) void pair_kernel(
    const int* __restrict__ pair_head, const int* __restrict__ pair_tail,
    const int* __restrict__ pair_rel,  const float* __restrict__ W_r2,
    const float* __restrict__ b_r2,    float* __restrict__ out)
{
    int w = threadIdx.x >> 5, lane = threadIdx.x & 31;
    int bp = blockIdx.x*8 + w;
    int b = bp >> 8;
    int h = pair_head[bp], t = pair_tail[bp], r = pair_rel[bp];
    const float* He = &g_He[(size_t)(b*EE+h)*256 + lane*8];
    const float* Te = &g_Te[(size_t)(b*EE+t)*256 + lane*8];
    const float* Rp = &g_Rp[r*256 + lane*8];
    const float* Cp = &g_clsp[b*256 + lane*8];
    float s = 0.f;
    #pragma unroll
    for (int q=0;q<2;q++){
        float4 a  = *(const float4*)(He + 4*q);
        float4 bb = *(const float4*)(Te + 4*q);
        float4 c  = *(const float4*)(Rp + 4*q);
        float4 d  = *(const float4*)(Cp + 4*q);
        float4 w4 = *(const float4*)&W_r2[lane*8 + 4*q];
        float h0 = fmaxf(a.x+bb.x+c.x+d.x, 0.f); s = fmaf(h0, w4.x, s);
        float h1 = fmaxf(a.y+bb.y+c.y+d.y, 0.f); s = fmaf(h1, w4.y, s);
        float h2 = fmaxf(a.z+bb.z+c.z+d.z, 0.f); s = fmaf(h2, w4.z, s);
        float h3 = fmaxf(a.w+bb.w+c.w+d.w, 0.f); s = fmaf(h3, w4.w, s);
    }
    #pragma unroll
    for (int off=16;off>0;off>>=1) s += __shfl_xor_sync(0xffffffffu,s,off);
    if (lane == 0) out[NER_TOTAL + bp] = s + b_r2[0];
}

// ============================================================================
extern "C" void kernel_launch(void* const* d_in, const int* in_sizes, int n_in,
                              void* d_out, int out_size)
{
    (void)in_sizes; (void)n_in; (void)out_size;
    const float* seq       = (const float*)d_in[0];
    const int*   span_start= (const int*)d_in[1];
    const int*   span_len  = (const int*)d_in[2];
    const int*   ent_type  = (const int*)d_in[3];
    const int*   pair_head = (const int*)d_in[4];
    const int*   pair_tail = (const int*)d_in[5];
    const int*   pair_rel  = (const int*)d_in[6];
    const float* W_ner1    = (const float*)d_in[7];
    const float* b_ner1    = (const float*)d_in[8];
    const float* W_ner2    = (const float*)d_in[9];
    const float* b_ner2    = (const float*)d_in[10];
    const float* type_emb  = (const float*)d_in[11];
    const float* W_g1      = (const float*)d_in[12];
    const float* a_src1    = (const float*)d_in[13];
    const float* a_dst1    = (const float*)d_in[14];
    const float* b_g1      = (const float*)d_in[15];
    const float* g1_gamma  = (const float*)d_in[16];
    const float* g1_beta   = (const float*)d_in[17];
    const float* W_g2      = (const float*)d_in[18];
    const float* a_src2    = (const float*)d_in[19];
    const float* a_dst2    = (const float*)d_in[20];
    const float* b_g2      = (const float*)d_in[21];
    const float* g2_gamma  = (const float*)d_in[22];
    const float* g2_beta   = (const float*)d_in[23];
    const float* rel_emb   = (const float*)d_in[24];
    const float* W_r1      = (const float*)d_in[25];
    const float* b_r1      = (const float*)d_in[26];
    const float* W_r2      = (const float*)d_in[27];
    const float* b_r2      = (const float*)d_in[28];
    float* out = (float*)d_out;

    static cudaStream_t sA = nullptr;
    static cudaEvent_t evRoot = nullptr, evT = nullptr, evA = nullptr;
    if (!sA){
        cudaStreamCreateWithFlags(&sA, cudaStreamNonBlocking);
        cudaEventCreateWithFlags(&evRoot, cudaEventDisableTiming);
        cudaEventCreateWithFlags(&evT, cudaEventDisableTiming);
        cudaEventCreateWithFlags(&evA, cudaEventDisableTiming);
    }

    uint4 *pSh, *pSl, *pXh, *pXl, *pW1h, *pW1l, *pG1h, *pG1l;
    cudaGetSymbolAddress((void**)&pSh,  g_pSh);
    cudaGetSymbolAddress((void**)&pSl,  g_pSl);
    cudaGetSymbolAddress((void**)&pXh,  g_pXh);
    cudaGetSymbolAddress((void**)&pXl,  g_pXl);
    cudaGetSymbolAddress((void**)&pW1h, g_pW1h);
    cudaGetSymbolAddress((void**)&pW1l, g_pW1l);
    cudaGetSymbolAddress((void**)&pG1h, g_pG1h);
    cudaGetSymbolAddress((void**)&pG1l, g_pG1l);
    float *xsrc;
    cudaGetSymbolAddress((void**)&xsrc, g_x);

    cudaFuncSetAttribute((const void*)pool_kernel,
                         cudaFuncAttributeMaxDynamicSharedMemorySize, 65536);
    cudaFuncSetAttribute((const void*)mma_merged,
                         cudaFuncAttributeMaxDynamicSharedMemorySize, 65536);

    // ---- fork: packs + cls/rp on side stream (record-before-wait only) ----
    cudaEventRecord(evRoot, 0);
    cudaStreamWaitEvent(sA, evRoot, 0);
    pack_b<<<96, 256, 0, sA>>>(W_ner1, 256, pW1h, pW1l);
    pack_b<<<192, 256, 0, sA>>>(W_g1, 512, pG1h, pG1l);
    pack_a<<<(1536*48)/8, 256, 0, sA>>>(seq, pSh, pSl);
    cudaEventRecord(evT, sA);
    cls_kernel<<<dim3(BB, 4), 256, 0, sA>>>(seq, W_r1, b_r1);
    rp_kernel<<<9, 256, 0, sA>>>(rel_emb, W_r1);
    cudaEventRecord(evA, sA);

    // ---- main chain ----
    pool_kernel<<<BB*EE, 256, LL*HH*sizeof(float)>>>(seq, span_start, span_len,
                                                     ent_type, type_emb);
    pack_a<<<(384*48)/8, 256>>>(xsrc, pXh, pXl);
    sim_kernel<<<BB*2, 128>>>();
    topk_kernel<<<(BB*EE)/8, 256>>>();

    cudaStreamWaitEvent(0, evT, 0);
    mma_merged<<<576, 256, 65536>>>(pSh, pSl, pW1h, pW1l,
                                    pXh, pXl, pG1h, pG1l, b_ner1,
                                    a_src1, a_dst1);
    ner_head<<<(BB*SS)/8, 256>>>(W_ner2, b_ner2, out);
    att1_kernel<<<BB*EE, 128>>>(b_g1, g1_gamma, g1_beta, W_g2, a_src2, a_dst2);
    att2_kernel<<<BB*EE, 128>>>(b_g2, g2_gamma, g2_beta);
    gemm_kernel<<<dim3((BB*EE)/64, 2, 2), 128>>>(W_r1, 256, 64);
    cudaStreamWaitEvent(0, evA, 0);
    pair_kernel<<<(BB*PP)/8, 256>>>(pair_head, pair_tail, pair_rel,
                                    W_r2, b_r2, out);
}